// round 5
// baseline (speedup 1.0000x reference)
#include <cuda_runtime.h>

// EOQLinear int4-GEMV, N=K=8192, qblock=128.
// Harness promotes float16 arrays to float32: x, scales, out are float32.
// packed_w: int32 in [0,256): lo nibble -> even k, hi nibble -> odd k, offset-8.
// HBM-bound: 128MB of packed_w read once.

constexpr int KDIM  = 8192;
constexpr int WORDS = KDIM / 2;   // 4096 int32 words per row
constexpr int QBLK  = 64;         // quant blocks per row (K/128)
constexpr int TPB   = 256;
constexpr int RPB   = 8;          // rows per CTA

// (w & 0xF) | 0x4B000000 is exactly float(2^23 + lo); subtract 2^23+8 -> exact lo-8.
__device__ __forceinline__ float dec_lo(int w) {
    return __int_as_float((w & 0xF) | 0x4B000000) - 8388616.0f;
}
__device__ __forceinline__ float dec_hi(int w) {
    return __int_as_float(((w >> 4) & 0xF) | 0x4B000000) - 8388616.0f;
}

__global__ __launch_bounds__(TPB, 2)
void q4_gemv_kernel(const float* __restrict__ x,       // [8192] fp32
                    const int4*  __restrict__ wq,      // packed_w as int4 (4 words / 16B)
                    const float* __restrict__ scales,  // [N, 64] fp32
                    float* __restrict__ out)           // [N] fp32
{
    __shared__ float red[RPB][TPB];

    const int t = threadIdx.x;
    const int g = t >> 4;   // 0..15: this thread's qblock group (owns qblocks 4g..4g+3)
    const int s = t & 15;   // position inside each qblock (words 4s..4s+3)

    // ---- Preload this thread's fixed x slice into registers, once. ----
    // Chunk i covers words (4g+i)*64 + 4s..+3  -> x floats at (4g+i)*128 + 8s..+7
    float xr[32];
#pragma unroll
    for (int i = 0; i < 4; i++) {
        const float4 a = *reinterpret_cast<const float4*>(x + (4 * g + i) * 128 + s * 8);
        const float4 b = *reinterpret_cast<const float4*>(x + (4 * g + i) * 128 + s * 8 + 4);
        xr[i * 8 + 0] = a.x; xr[i * 8 + 1] = a.y;
        xr[i * 8 + 2] = a.z; xr[i * 8 + 3] = a.w;
        xr[i * 8 + 4] = b.x; xr[i * 8 + 5] = b.y;
        xr[i * 8 + 6] = b.z; xr[i * 8 + 7] = b.w;
    }

    const int row0 = blockIdx.x * RPB;

#pragma unroll 2
    for (int r = 0; r < RPB; r++) {
        const int row = row0 + r;
        const int4* wp = wq + (long)row * (WORDS / 4);

        // This thread's 4 qblock scales are contiguous: one 16B load.
        const float4 sv = *reinterpret_cast<const float4*>(scales + (long)row * QBLK + 4 * g);
        const float sc[4] = {sv.x, sv.y, sv.z, sv.w};

        float racc = 0.0f;
#pragma unroll
        for (int i = 0; i < 4; i++) {
            // int4 index = word/4 = ((4g+i)*64 + 4s)/4 = (4g+i)*16 + s
            const int4 wv = wp[(4 * g + i) * 16 + s];
            float p = 0.0f;
            p = fmaf(dec_lo(wv.x), xr[i * 8 + 0], p);
            p = fmaf(dec_hi(wv.x), xr[i * 8 + 1], p);
            p = fmaf(dec_lo(wv.y), xr[i * 8 + 2], p);
            p = fmaf(dec_hi(wv.y), xr[i * 8 + 3], p);
            p = fmaf(dec_lo(wv.z), xr[i * 8 + 4], p);
            p = fmaf(dec_hi(wv.z), xr[i * 8 + 5], p);
            p = fmaf(dec_lo(wv.w), xr[i * 8 + 6], p);
            p = fmaf(dec_hi(wv.w), xr[i * 8 + 7], p);
            // One multiply by the block scale per qblock (factored-scale form).
            racc = fmaf(p, sc[i], racc);
        }
        red[r][t] = racc;
    }
    __syncthreads();

    // ---- Reduce: warp w sums row (row0 + w) across the 256 threads. ----
    const int wid = t >> 5, lane = t & 31;
    float v = 0.0f;
#pragma unroll
    for (int k = 0; k < TPB / 32; k++) v += red[wid][lane + 32 * k];
#pragma unroll
    for (int o = 16; o > 0; o >>= 1) v += __shfl_xor_sync(0xFFFFFFFFu, v, o);
    if (lane == 0) out[row0 + wid] = v;
}

extern "C" void kernel_launch(void* const* d_in, const int* in_sizes, int n_in,
                              void* d_out, int out_size) {
    const float* x      = (const float*)d_in[0];   // fp16->fp32 promoted [8192]
    const int4*  wq     = (const int4*)d_in[1];    // int32 [8192, 4096] viewed as int4
    const float* scales = (const float*)d_in[2];   // fp16->fp32 promoted [8192, 64]
    // d_in[3] = qblock_size (128), compile-time constant here.
    float* out = (float*)d_out;

    const int n_rows = out_size;                   // 8192
    q4_gemv_kernel<<<n_rows / RPB, TPB>>>(x, wq, scales, out);
}

// round 6
// speedup vs baseline: 1.0755x; 1.0755x over previous
#include <cuda_runtime.h>

// EOQLinear int4-GEMV, N=K=8192, qblock=128.
// Harness promotes float16 arrays to float32: x, scales, out are float32.
// packed_w: int32 in [0,256): lo nibble -> even k, hi nibble -> odd k, offset-8.
// HBM-bound: 128MB of packed_w read once. This revision targets latency hiding:
// 512 threads/CTA, <=64 regs -> 32 warps/SM (2x prior), same coalescing.

constexpr int KDIM  = 8192;
constexpr int WORDS = KDIM / 2;   // 4096 int32 words per row
constexpr int QBLK  = 64;         // quant blocks per row (K/128)
constexpr int TPB   = 512;
constexpr int RPB   = 16;         // rows per CTA (one per warp for the reduction)

// (w & 0xF) | 0x4B000000 is exactly float(2^23 + lo); subtract 2^23+8 -> exact lo-8.
__device__ __forceinline__ float dec_lo(int w) {
    return __int_as_float((w & 0xF) | 0x4B000000) - 8388616.0f;
}
__device__ __forceinline__ float dec_hi(int w) {
    return __int_as_float(((w >> 4) & 0xF) | 0x4B000000) - 8388616.0f;
}

__global__ __launch_bounds__(TPB, 2)
void q4_gemv_kernel(const float* __restrict__ x,       // [8192] fp32
                    const int4*  __restrict__ wq,      // packed_w as int4 (4 words / 16B)
                    const float* __restrict__ scales,  // [N, 64] fp32
                    float* __restrict__ out)           // [N] fp32
{
    __shared__ float red[RPB][TPB];

    const int t = threadIdx.x;
    const int g = t >> 4;   // 0..31: this thread's qblock group (owns qblocks 2g, 2g+1)
    const int s = t & 15;   // position inside each qblock (words 4s..4s+3)

    // ---- Preload this thread's fixed x slice into registers, once. ----
    // Chunk i in {0,1} covers words (2g+i)*64 + 4s..+3 -> x floats (2g+i)*128 + 8s..+7
    float xr[16];
#pragma unroll
    for (int i = 0; i < 2; i++) {
        const float4 a = *reinterpret_cast<const float4*>(x + (2 * g + i) * 128 + s * 8);
        const float4 b = *reinterpret_cast<const float4*>(x + (2 * g + i) * 128 + s * 8 + 4);
        xr[i * 8 + 0] = a.x; xr[i * 8 + 1] = a.y;
        xr[i * 8 + 2] = a.z; xr[i * 8 + 3] = a.w;
        xr[i * 8 + 4] = b.x; xr[i * 8 + 5] = b.y;
        xr[i * 8 + 6] = b.z; xr[i * 8 + 7] = b.w;
    }

    const int row0 = blockIdx.x * RPB;

#pragma unroll 4
    for (int r = 0; r < RPB; r++) {
        const int row = row0 + r;
        const int4* wp = wq + (long)row * (WORDS / 4);

        // This thread's 2 qblock scales are contiguous: one 8B load.
        const float2 sv = *reinterpret_cast<const float2*>(scales + (long)row * QBLK + 2 * g);
        const float sc[2] = {sv.x, sv.y};

        float racc = 0.0f;
#pragma unroll
        for (int i = 0; i < 2; i++) {
            // int4 index = word/4 = ((2g+i)*64 + 4s)/4 = (2g+i)*16 + s
            const int4 wv = wp[(2 * g + i) * 16 + s];
            float p = 0.0f;
            p = fmaf(dec_lo(wv.x), xr[i * 8 + 0], p);
            p = fmaf(dec_hi(wv.x), xr[i * 8 + 1], p);
            p = fmaf(dec_lo(wv.y), xr[i * 8 + 2], p);
            p = fmaf(dec_hi(wv.y), xr[i * 8 + 3], p);
            p = fmaf(dec_lo(wv.z), xr[i * 8 + 4], p);
            p = fmaf(dec_hi(wv.z), xr[i * 8 + 5], p);
            p = fmaf(dec_lo(wv.w), xr[i * 8 + 6], p);
            p = fmaf(dec_hi(wv.w), xr[i * 8 + 7], p);
            // One multiply by the block scale per qblock (factored-scale form).
            racc = fmaf(p, sc[i], racc);
        }
        red[r][t] = racc;
    }
    __syncthreads();

    // ---- Reduce: warp w sums row (row0 + w) across the 512 threads. ----
    const int wid = t >> 5, lane = t & 31;
    float v = 0.0f;
#pragma unroll
    for (int k = 0; k < TPB / 32; k++) v += red[wid][lane + 32 * k];
#pragma unroll
    for (int o = 16; o > 0; o >>= 1) v += __shfl_xor_sync(0xFFFFFFFFu, v, o);
    if (lane == 0) out[row0 + wid] = v;
}

extern "C" void kernel_launch(void* const* d_in, const int* in_sizes, int n_in,
                              void* d_out, int out_size) {
    const float* x      = (const float*)d_in[0];   // fp16->fp32 promoted [8192]
    const int4*  wq     = (const int4*)d_in[1];    // int32 [8192, 4096] viewed as int4
    const float* scales = (const float*)d_in[2];   // fp16->fp32 promoted [8192, 64]
    // d_in[3] = qblock_size (128), compile-time constant here.
    float* out = (float*)d_out;

    const int n_rows = out_size;                   // 8192
    q4_gemv_kernel<<<n_rows / RPB, TPB>>>(x, wq, scales, out);
}